// round 12
// baseline (speedup 1.0000x reference)
#include <cuda_runtime.h>

// Problem constants (fixed by the reference setup_inputs)
#define BB 4
#define HH 384
#define WW 512
#define CC 64
#define CH4 (CC / 4)        // 16 float4 chunks per pixel
#define PIXB 64             // pixels per block
#define THREADS 512         // 64 pixels x 8 threads; each thread does 2 float4 chunks

__global__ void __launch_bounds__(THREADS, 4)
warp_bilinear_kernel(const float2* __restrict__ flow,    // [B,H,W] of float2
                     const float4* __restrict__ feat,    // [B,H,W,C/4] of float4
                     const float*  __restrict__ mask,    // [H,W]
                     float4*       __restrict__ out)     // [B,H,W,C/4]
{
    const unsigned tid  = threadIdx.x;
    const unsigned lane = tid & 7u;        // chunk group: handles lane and lane+8
    const unsigned pi   = tid >> 3;        // pixel within block [0,64)
    const unsigned px   = blockIdx.x * PIXB + pi;
    const unsigned py   = blockIdx.y;
    const unsigned b    = blockIdx.z;

    const unsigned hw  = py * WW + px;
    const unsigned pix = b * (HH * WW) + hw;

    // Leader lane of each 8-thread pixel group loads flow+mask; broadcast via shfl.
    float flx, fly, m;
    if (lane == 0) {
        const float2 t = __ldcs(&flow[pix]);
        flx = t.x; fly = t.y;
        m = mask[hw];
    }
    const unsigned src = (tid & 31u) & ~7u;   // group leader's lane within the warp
    flx = __shfl_sync(0xffffffffu, flx, src);
    fly = __shfl_sync(0xffffffffu, fly, src);
    m   = __shfl_sync(0xffffffffu, m,   src);

    const float xt = (float)px + flx;
    const float yt = (float)py + fly;

    // Faithful to reference arithmetic: (2*t/(D-1) - 1 + 1) * 0.5 * D
    const float x = (2.0f * xt / (float)(WW - 1) - 1.0f + 1.0f) * 0.5f * (float)WW;
    const float y = (2.0f * yt / (float)(HH - 1) - 1.0f + 1.0f) * 0.5f * (float)HH;

    int x0i = (int)floorf(x);
    int y0i = (int)floorf(y);
    x0i = min(max(x0i, 0), WW - 1);
    y0i = min(max(y0i, 0), HH - 1);
    const int x1i = min(x0i + 1, WW - 1);
    const int y1i = min(y0i + 1, HH - 1);

    const float x0f = (float)x0i, x1f = (float)x1i;
    const float y0f = (float)y0i, y1f = (float)y1i;

    const float wam = (x1f - x) * (y1f - y) * m;
    const float wbm = (x1f - x) * (y - y0f) * m;
    const float wcm = (x - x0f) * (y1f - y) * m;
    const float wdm = (x - x0f) * (y - y0f) * m;

    // 32-bit indexing (feature is 201 MB; all element offsets < 2^26)
    const unsigned base = b * (HH * WW) * CH4 + lane;
    const float4* pa = feat + base + (unsigned)(y0i * WW + x0i) * CH4;
    const float4* pb = feat + base + (unsigned)(y1i * WW + x0i) * CH4;
    const float4* pc = feat + base + (unsigned)(y0i * WW + x1i) * CH4;
    const float4* pd = feat + base + (unsigned)(y1i * WW + x1i) * CH4;

    // Two independent chunk sets (lane, lane+8) -> 8 outstanding gathers
    const float4 fa0 = __ldg(pa + 0), fa1 = __ldg(pa + 8);
    const float4 fb0 = __ldg(pb + 0), fb1 = __ldg(pb + 8);
    const float4 fc0 = __ldg(pc + 0), fc1 = __ldg(pc + 8);
    const float4 fd0 = __ldg(pd + 0), fd1 = __ldg(pd + 8);

    float4 r0, r1;
    r0.x = wam * fa0.x + wbm * fb0.x + wcm * fc0.x + wdm * fd0.x;
    r0.y = wam * fa0.y + wbm * fb0.y + wcm * fc0.y + wdm * fd0.y;
    r0.z = wam * fa0.z + wbm * fb0.z + wcm * fc0.z + wdm * fd0.z;
    r0.w = wam * fa0.w + wbm * fb0.w + wcm * fc0.w + wdm * fd0.w;

    r1.x = wam * fa1.x + wbm * fb1.x + wcm * fc1.x + wdm * fd1.x;
    r1.y = wam * fa1.y + wbm * fb1.y + wcm * fc1.y + wdm * fd1.y;
    r1.z = wam * fa1.z + wbm * fb1.z + wcm * fc1.z + wdm * fd1.z;
    r1.w = wam * fa1.w + wbm * fb1.w + wcm * fc1.w + wdm * fd1.w;

    float4* po = out + pix * CH4 + lane;
    __stcs(po + 0, r0);
    __stcs(po + 8, r1);
}

extern "C" void kernel_launch(void* const* d_in, const int* in_sizes, int n_in,
                              void* d_out, int out_size)
{
    const float2* flow = (const float2*)d_in[0];   // w: [B,H,W,2]
    const float4* feat = (const float4*)d_in[1];   // feature: [B,H,W,C]
    const float*  mask = (const float*)d_in[2];    // mask: [H,W]
    float4* out = (float4*)d_out;

    dim3 grid(WW / PIXB, HH, BB);                  // (8, 384, 4)
    warp_bilinear_kernel<<<grid, THREADS>>>(flow, feat, mask, out);
}

// round 13
// speedup vs baseline: 1.0338x; 1.0338x over previous
#include <cuda_runtime.h>

// Problem constants (fixed by the reference setup_inputs)
#define BB 4
#define HH 384
#define WW 512
#define CC 64
#define CH4 (CC / 4)        // 16 float4 chunks per pixel
#define PIXB 32             // pixels per block
#define THREADS 256         // 32 pixels x 8 threads; each thread does 2 float4 chunks

__global__ void __launch_bounds__(THREADS, 8)
warp_bilinear_kernel(const float2* __restrict__ flow,    // [B,H,W] of float2
                     const float4* __restrict__ feat,    // [B,H,W,C/4] of float4
                     const float*  __restrict__ mask,    // [H,W]
                     float4*       __restrict__ out)     // [B,H,W,C/4]
{
    const unsigned lane = threadIdx.x & 7u;        // chunk group: handles lane and lane+8
    const unsigned pi   = threadIdx.x >> 3;        // pixel within block [0,32)
    const unsigned px   = blockIdx.x * PIXB + pi;
    const unsigned py   = blockIdx.y;
    const unsigned b    = blockIdx.z;

    const unsigned hw  = py * WW + px;
    const unsigned pix = b * (HH * WW) + hw;

    const float2 fl = __ldcs(&flow[pix]);
    const float xt = (float)px + fl.x;
    const float yt = (float)py + fl.y;

    // Faithful to reference arithmetic: (2*t/(D-1) - 1 + 1) * 0.5 * D
    const float x = (2.0f * xt / (float)(WW - 1) - 1.0f + 1.0f) * 0.5f * (float)WW;
    const float y = (2.0f * yt / (float)(HH - 1) - 1.0f + 1.0f) * 0.5f * (float)HH;

    int x0i = (int)floorf(x);
    int y0i = (int)floorf(y);
    x0i = min(max(x0i, 0), WW - 1);
    y0i = min(max(y0i, 0), HH - 1);
    const int x1i = min(x0i + 1, WW - 1);
    const int y1i = min(y0i + 1, HH - 1);

    const float x0f = (float)x0i, x1f = (float)x1i;
    const float y0f = (float)y0i, y1f = (float)y1i;

    const float m = mask[hw];
    const float wam = (x1f - x) * (y1f - y) * m;
    const float wbm = (x1f - x) * (y - y0f) * m;
    const float wcm = (x - x0f) * (y1f - y) * m;
    const float wdm = (x - x0f) * (y - y0f) * m;

    // 32-bit indexing (feature is 201 MB; all element offsets < 2^26)
    const unsigned base = b * (HH * WW) * CH4 + lane;
    const float4* pa = feat + base + (unsigned)(y0i * WW + x0i) * CH4;
    const float4* pb = feat + base + (unsigned)(y1i * WW + x0i) * CH4;
    const float4* pc = feat + base + (unsigned)(y0i * WW + x1i) * CH4;
    const float4* pd = feat + base + (unsigned)(y1i * WW + x1i) * CH4;

    // Two independent chunk sets (lane, lane+8) -> 8 outstanding gathers;
    // each pixel-group's corner fetch is one contiguous 256B segment.
    const float4 fa0 = __ldg(pa + 0), fa1 = __ldg(pa + 8);
    const float4 fb0 = __ldg(pb + 0), fb1 = __ldg(pb + 8);
    const float4 fc0 = __ldg(pc + 0), fc1 = __ldg(pc + 8);
    const float4 fd0 = __ldg(pd + 0), fd1 = __ldg(pd + 8);

    float4 r0, r1;
    r0.x = wam * fa0.x + wbm * fb0.x + wcm * fc0.x + wdm * fd0.x;
    r0.y = wam * fa0.y + wbm * fb0.y + wcm * fc0.y + wdm * fd0.y;
    r0.z = wam * fa0.z + wbm * fb0.z + wcm * fc0.z + wdm * fd0.z;
    r0.w = wam * fa0.w + wbm * fb0.w + wcm * fc0.w + wdm * fd0.w;

    r1.x = wam * fa1.x + wbm * fb1.x + wcm * fc1.x + wdm * fd1.x;
    r1.y = wam * fa1.y + wbm * fb1.y + wcm * fc1.y + wdm * fd1.y;
    r1.z = wam * fa1.z + wbm * fb1.z + wcm * fc1.z + wdm * fd1.z;
    r1.w = wam * fa1.w + wbm * fb1.w + wcm * fc1.w + wdm * fd1.w;

    float4* po = out + pix * CH4 + lane;
    __stcs(po + 0, r0);
    __stcs(po + 8, r1);
}

extern "C" void kernel_launch(void* const* d_in, const int* in_sizes, int n_in,
                              void* d_out, int out_size)
{
    const float2* flow = (const float2*)d_in[0];   // w: [B,H,W,2]
    const float4* feat = (const float4*)d_in[1];   // feature: [B,H,W,C]
    const float*  mask = (const float*)d_in[2];    // mask: [H,W]
    float4* out = (float4*)d_out;

    dim3 grid(WW / PIXB, HH, BB);                  // (16, 384, 4)
    warp_bilinear_kernel<<<grid, THREADS>>>(flow, feat, mask, out);
}

// round 14
// speedup vs baseline: 1.0493x; 1.0150x over previous
#include <cuda_runtime.h>

// Problem constants (fixed by the reference setup_inputs)
#define BB 4
#define HH 384
#define WW 512
#define CC 64
#define CH4 (CC / 4)        // 16 float4 chunks per pixel
#define PIXB 16             // pixels per block
#define THREADS 128         // 16 pixels x 8 threads; each thread does 2 float4 chunks

__global__ void __launch_bounds__(THREADS, 16)
warp_bilinear_kernel(const float2* __restrict__ flow,    // [B,H,W] of float2
                     const float4* __restrict__ feat,    // [B,H,W,C/4] of float4
                     const float*  __restrict__ mask,    // [H,W]
                     float4*       __restrict__ out)     // [B,H,W,C/4]
{
    const unsigned lane = threadIdx.x & 7u;        // chunk group: handles lane and lane+8
    const unsigned pi   = threadIdx.x >> 3;        // pixel within block [0,16)
    const unsigned px   = blockIdx.x * PIXB + pi;
    const unsigned py   = blockIdx.y;
    const unsigned b    = blockIdx.z;

    const unsigned hw  = py * WW + px;
    const unsigned pix = b * (HH * WW) + hw;

    const float2 fl = __ldcs(&flow[pix]);
    const float xt = (float)px + fl.x;
    const float yt = (float)py + fl.y;

    // Faithful to reference arithmetic: (2*t/(D-1) - 1 + 1) * 0.5 * D
    const float x = (2.0f * xt / (float)(WW - 1) - 1.0f + 1.0f) * 0.5f * (float)WW;
    const float y = (2.0f * yt / (float)(HH - 1) - 1.0f + 1.0f) * 0.5f * (float)HH;

    int x0i = (int)floorf(x);
    int y0i = (int)floorf(y);
    x0i = min(max(x0i, 0), WW - 1);
    y0i = min(max(y0i, 0), HH - 1);
    const int x1i = min(x0i + 1, WW - 1);
    const int y1i = min(y0i + 1, HH - 1);

    const float x0f = (float)x0i, x1f = (float)x1i;
    const float y0f = (float)y0i, y1f = (float)y1i;

    const float m = mask[hw];
    const float wam = (x1f - x) * (y1f - y) * m;
    const float wbm = (x1f - x) * (y - y0f) * m;
    const float wcm = (x - x0f) * (y1f - y) * m;
    const float wdm = (x - x0f) * (y - y0f) * m;

    // 32-bit indexing (feature is 201 MB; all element offsets < 2^26)
    const unsigned base = b * (HH * WW) * CH4 + lane;
    const float4* pa = feat + base + (unsigned)(y0i * WW + x0i) * CH4;
    const float4* pb = feat + base + (unsigned)(y1i * WW + x0i) * CH4;
    const float4* pc = feat + base + (unsigned)(y0i * WW + x1i) * CH4;
    const float4* pd = feat + base + (unsigned)(y1i * WW + x1i) * CH4;

    // Two independent chunk sets (lane, lane+8) -> 8 outstanding gathers;
    // each pixel-group's corner fetch is one contiguous 256B segment.
    const float4 fa0 = __ldg(pa + 0), fa1 = __ldg(pa + 8);
    const float4 fb0 = __ldg(pb + 0), fb1 = __ldg(pb + 8);
    const float4 fc0 = __ldg(pc + 0), fc1 = __ldg(pc + 8);
    const float4 fd0 = __ldg(pd + 0), fd1 = __ldg(pd + 8);

    float4 r0, r1;
    r0.x = wam * fa0.x + wbm * fb0.x + wcm * fc0.x + wdm * fd0.x;
    r0.y = wam * fa0.y + wbm * fb0.y + wcm * fc0.y + wdm * fd0.y;
    r0.z = wam * fa0.z + wbm * fb0.z + wcm * fc0.z + wdm * fd0.z;
    r0.w = wam * fa0.w + wbm * fb0.w + wcm * fc0.w + wdm * fd0.w;

    r1.x = wam * fa1.x + wbm * fb1.x + wcm * fc1.x + wdm * fd1.x;
    r1.y = wam * fa1.y + wbm * fb1.y + wcm * fc1.y + wdm * fd1.y;
    r1.z = wam * fa1.z + wbm * fb1.z + wcm * fc1.z + wdm * fd1.z;
    r1.w = wam * fa1.w + wbm * fb1.w + wcm * fc1.w + wdm * fd1.w;

    float4* po = out + pix * CH4 + lane;
    __stcs(po + 0, r0);
    __stcs(po + 8, r1);
}

extern "C" void kernel_launch(void* const* d_in, const int* in_sizes, int n_in,
                              void* d_out, int out_size)
{
    const float2* flow = (const float2*)d_in[0];   // w: [B,H,W,2]
    const float4* feat = (const float4*)d_in[1];   // feature: [B,H,W,C]
    const float*  mask = (const float*)d_in[2];    // mask: [H,W]
    float4* out = (float4*)d_out;

    dim3 grid(WW / PIXB, HH, BB);                  // (32, 384, 4)
    warp_bilinear_kernel<<<grid, THREADS>>>(flow, feat, mask, out);
}

// round 15
// speedup vs baseline: 1.0591x; 1.0093x over previous
#include <cuda_runtime.h>

// Problem constants (fixed by the reference setup_inputs)
#define BB 4
#define HH 384
#define WW 512
#define CC 64
#define CH4 (CC / 4)        // 16 float4 chunks per pixel
#define PIXB 8              // pixels per block
#define THREADS 64          // 8 pixels x 8 threads; each thread does 2 float4 chunks

__global__ void __launch_bounds__(THREADS, 32)
warp_bilinear_kernel(const float2* __restrict__ flow,    // [B,H,W] of float2
                     const float4* __restrict__ feat,    // [B,H,W,C/4] of float4
                     const float*  __restrict__ mask,    // [H,W]
                     float4*       __restrict__ out)     // [B,H,W,C/4]
{
    const unsigned lane = threadIdx.x & 7u;        // chunk group: handles lane and lane+8
    const unsigned pi   = threadIdx.x >> 3;        // pixel within block [0,8)
    const unsigned px   = blockIdx.x * PIXB + pi;
    const unsigned py   = blockIdx.y;
    const unsigned b    = blockIdx.z;

    const unsigned hw  = py * WW + px;
    const unsigned pix = b * (HH * WW) + hw;

    const float2 fl = __ldcs(&flow[pix]);
    const float xt = (float)px + fl.x;
    const float yt = (float)py + fl.y;

    // Faithful to reference arithmetic: (2*t/(D-1) - 1 + 1) * 0.5 * D
    const float x = (2.0f * xt / (float)(WW - 1) - 1.0f + 1.0f) * 0.5f * (float)WW;
    const float y = (2.0f * yt / (float)(HH - 1) - 1.0f + 1.0f) * 0.5f * (float)HH;

    int x0i = (int)floorf(x);
    int y0i = (int)floorf(y);
    x0i = min(max(x0i, 0), WW - 1);
    y0i = min(max(y0i, 0), HH - 1);
    const int x1i = min(x0i + 1, WW - 1);
    const int y1i = min(y0i + 1, HH - 1);

    const float x0f = (float)x0i, x1f = (float)x1i;
    const float y0f = (float)y0i, y1f = (float)y1i;

    const float m = mask[hw];
    const float wam = (x1f - x) * (y1f - y) * m;
    const float wbm = (x1f - x) * (y - y0f) * m;
    const float wcm = (x - x0f) * (y1f - y) * m;
    const float wdm = (x - x0f) * (y - y0f) * m;

    // 32-bit indexing (feature is 201 MB; all element offsets < 2^26)
    const unsigned base = b * (HH * WW) * CH4 + lane;
    const float4* pa = feat + base + (unsigned)(y0i * WW + x0i) * CH4;
    const float4* pb = feat + base + (unsigned)(y1i * WW + x0i) * CH4;
    const float4* pc = feat + base + (unsigned)(y0i * WW + x1i) * CH4;
    const float4* pd = feat + base + (unsigned)(y1i * WW + x1i) * CH4;

    // Two independent chunk sets (lane, lane+8) -> 8 outstanding gathers;
    // each pixel-group's corner fetch is one contiguous 256B segment.
    const float4 fa0 = __ldg(pa + 0), fa1 = __ldg(pa + 8);
    const float4 fb0 = __ldg(pb + 0), fb1 = __ldg(pb + 8);
    const float4 fc0 = __ldg(pc + 0), fc1 = __ldg(pc + 8);
    const float4 fd0 = __ldg(pd + 0), fd1 = __ldg(pd + 8);

    float4 r0, r1;
    r0.x = wam * fa0.x + wbm * fb0.x + wcm * fc0.x + wdm * fd0.x;
    r0.y = wam * fa0.y + wbm * fb0.y + wcm * fc0.y + wdm * fd0.y;
    r0.z = wam * fa0.z + wbm * fb0.z + wcm * fc0.z + wdm * fd0.z;
    r0.w = wam * fa0.w + wbm * fb0.w + wcm * fc0.w + wdm * fd0.w;

    r1.x = wam * fa1.x + wbm * fb1.x + wcm * fc1.x + wdm * fd1.x;
    r1.y = wam * fa1.y + wbm * fb1.y + wcm * fc1.y + wdm * fd1.y;
    r1.z = wam * fa1.z + wbm * fb1.z + wcm * fc1.z + wdm * fd1.z;
    r1.w = wam * fa1.w + wbm * fb1.w + wcm * fc1.w + wdm * fd1.w;

    float4* po = out + pix * CH4 + lane;
    __stcs(po + 0, r0);
    __stcs(po + 8, r1);
}

extern "C" void kernel_launch(void* const* d_in, const int* in_sizes, int n_in,
                              void* d_out, int out_size)
{
    const float2* flow = (const float2*)d_in[0];   // w: [B,H,W,2]
    const float4* feat = (const float4*)d_in[1];   // feature: [B,H,W,C]
    const float*  mask = (const float*)d_in[2];    // mask: [H,W]
    float4* out = (float4*)d_out;

    dim3 grid(WW / PIXB, HH, BB);                  // (64, 384, 4)
    warp_bilinear_kernel<<<grid, THREADS>>>(flow, feat, mask, out);
}

// round 16
// speedup vs baseline: 1.0615x; 1.0022x over previous
#include <cuda_runtime.h>

// Problem constants (fixed by the reference setup_inputs)
#define BB 4
#define HH 384
#define WW 512
#define CC 64
#define CH4 (CC / 4)        // 16 float4 chunks per pixel
#define PIXB 8              // pixels per block
#define THREADS 64          // 8 pixels x 8 threads; each thread does 2 float4 chunks

__global__ void __launch_bounds__(THREADS, 32)
warp_bilinear_kernel(const float2* __restrict__ flow,    // [B,H,W] of float2
                     const float4* __restrict__ feat,    // [B,H,W,C/4] of float4
                     const float*  __restrict__ mask,    // [H,W]
                     float4*       __restrict__ out)     // [B,H,W,C/4]
{
    const unsigned lane = threadIdx.x & 7u;        // chunk group: handles lane and lane+8
    const unsigned pi   = threadIdx.x >> 3;        // pixel within block [0,8)
    const unsigned px   = blockIdx.x * PIXB + pi;
    const unsigned py   = blockIdx.y;
    const unsigned b    = blockIdx.z;

    const unsigned hw  = py * WW + px;
    const unsigned pix = b * (HH * WW) + hw;

    const float2 fl = __ldcs(&flow[pix]);
    const float xt = (float)px + fl.x;
    const float yt = (float)py + fl.y;

    // Faithful to reference arithmetic: (2*t/(D-1) - 1 + 1) * 0.5 * D
    const float x = (2.0f * xt / (float)(WW - 1) - 1.0f + 1.0f) * 0.5f * (float)WW;
    const float y = (2.0f * yt / (float)(HH - 1) - 1.0f + 1.0f) * 0.5f * (float)HH;

    int x0i = (int)floorf(x);
    int y0i = (int)floorf(y);
    x0i = min(max(x0i, 0), WW - 1);
    y0i = min(max(y0i, 0), HH - 1);
    const int x1i = min(x0i + 1, WW - 1);
    const int y1i = min(y0i + 1, HH - 1);

    const float x0f = (float)x0i, x1f = (float)x1i;
    const float y0f = (float)y0i, y1f = (float)y1i;

    const float m = mask[hw];
    const float wam = (x1f - x) * (y1f - y) * m;
    const float wbm = (x1f - x) * (y - y0f) * m;
    const float wcm = (x - x0f) * (y1f - y) * m;
    const float wdm = (x - x0f) * (y - y0f) * m;

    // 32-bit indexing (feature is 201 MB; all element offsets < 2^26)
    const unsigned base = b * (HH * WW) * CH4 + lane;
    const float4* pa = feat + base + (unsigned)(y0i * WW + x0i) * CH4;
    const float4* pb = feat + base + (unsigned)(y1i * WW + x0i) * CH4;
    const float4* pc = feat + base + (unsigned)(y0i * WW + x1i) * CH4;
    const float4* pd = feat + base + (unsigned)(y1i * WW + x1i) * CH4;

    // Two independent chunk sets (lane, lane+8) -> 8 outstanding gathers;
    // each pixel-group's corner fetch is one contiguous 256B segment.
    const float4 fa0 = __ldg(pa + 0), fa1 = __ldg(pa + 8);
    const float4 fb0 = __ldg(pb + 0), fb1 = __ldg(pb + 8);
    const float4 fc0 = __ldg(pc + 0), fc1 = __ldg(pc + 8);
    const float4 fd0 = __ldg(pd + 0), fd1 = __ldg(pd + 8);

    float4 r0, r1;
    r0.x = wam * fa0.x + wbm * fb0.x + wcm * fc0.x + wdm * fd0.x;
    r0.y = wam * fa0.y + wbm * fb0.y + wcm * fc0.y + wdm * fd0.y;
    r0.z = wam * fa0.z + wbm * fb0.z + wcm * fc0.z + wdm * fd0.z;
    r0.w = wam * fa0.w + wbm * fb0.w + wcm * fc0.w + wdm * fd0.w;

    r1.x = wam * fa1.x + wbm * fb1.x + wcm * fc1.x + wdm * fd1.x;
    r1.y = wam * fa1.y + wbm * fb1.y + wcm * fc1.y + wdm * fd1.y;
    r1.z = wam * fa1.z + wbm * fb1.z + wcm * fc1.z + wdm * fd1.z;
    r1.w = wam * fa1.w + wbm * fb1.w + wcm * fc1.w + wdm * fd1.w;

    // Plain stores: let L2 aggregate full-line writebacks (vs .cs early demote).
    float4* po = out + pix * CH4 + lane;
    po[0] = r0;
    po[8] = r1;
}

extern "C" void kernel_launch(void* const* d_in, const int* in_sizes, int n_in,
                              void* d_out, int out_size)
{
    const float2* flow = (const float2*)d_in[0];   // w: [B,H,W,2]
    const float4* feat = (const float4*)d_in[1];   // feature: [B,H,W,C]
    const float*  mask = (const float*)d_in[2];    // mask: [H,W]
    float4* out = (float4*)d_out;

    dim3 grid(WW / PIXB, HH, BB);                  // (64, 384, 4)
    warp_bilinear_kernel<<<grid, THREADS>>>(flow, feat, mask, out);
}

// round 17
// speedup vs baseline: 1.0624x; 1.0009x over previous
#include <cuda_runtime.h>

// Problem constants (fixed by the reference setup_inputs)
#define BB 4
#define HH 384
#define WW 512
#define CC 64
#define CH4 (CC / 4)        // 16 float4 chunks per pixel
#define PIXB 8              // pixels per block
#define THREADS 64          // 8 pixels x 8 threads; each thread does 2 float4 chunks

__global__ void __launch_bounds__(THREADS, 32)
warp_bilinear_kernel(const float2* __restrict__ flow,    // [B,H,W] of float2
                     const float4* __restrict__ feat,    // [B,H,W,C/4] of float4
                     const float*  __restrict__ mask,    // [H,W]
                     float4*       __restrict__ out)     // [B,H,W,C/4]
{
    const unsigned lane = threadIdx.x & 7u;        // chunk group: handles lane and lane+8
    const unsigned pi   = threadIdx.x >> 3;        // pixel within block [0,8)
    const unsigned px   = blockIdx.x * PIXB + pi;
    const unsigned py   = blockIdx.y;
    const unsigned b    = blockIdx.z;

    const unsigned hw  = py * WW + px;
    const unsigned pix = b * (HH * WW) + hw;

    const float2 fl = __ldcs(&flow[pix]);
    const float xt = (float)px + fl.x;
    const float yt = (float)py + fl.y;

    // Faithful to reference arithmetic: (2*t/(D-1) - 1 + 1) * 0.5 * D
    const float x = (2.0f * xt / (float)(WW - 1) - 1.0f + 1.0f) * 0.5f * (float)WW;
    const float y = (2.0f * yt / (float)(HH - 1) - 1.0f + 1.0f) * 0.5f * (float)HH;

    int x0i = (int)floorf(x);
    int y0i = (int)floorf(y);
    x0i = min(max(x0i, 0), WW - 1);
    y0i = min(max(y0i, 0), HH - 1);
    const int x1i = min(x0i + 1, WW - 1);
    const int y1i = min(y0i + 1, HH - 1);

    const float x0f = (float)x0i, x1f = (float)x1i;
    const float y0f = (float)y0i, y1f = (float)y1i;

    const float m = mask[hw];
    const float wam = (x1f - x) * (y1f - y) * m;
    const float wbm = (x1f - x) * (y - y0f) * m;
    const float wcm = (x - x0f) * (y1f - y) * m;
    const float wdm = (x - x0f) * (y - y0f) * m;

    // 32-bit indexing (feature is 201 MB; all element offsets < 2^26)
    const unsigned base = b * (HH * WW) * CH4 + lane;
    const float4* pa = feat + base + (unsigned)(y0i * WW + x0i) * CH4;
    const float4* pb = feat + base + (unsigned)(y1i * WW + x0i) * CH4;
    const float4* pc = feat + base + (unsigned)(y0i * WW + x1i) * CH4;
    const float4* pd = feat + base + (unsigned)(y1i * WW + x1i) * CH4;

    // Two independent chunk sets (lane, lane+8) -> 8 outstanding gathers;
    // each pixel-group's corner fetch is one contiguous 256B segment.
    const float4 fa0 = __ldg(pa + 0), fa1 = __ldg(pa + 8);
    const float4 fb0 = __ldg(pb + 0), fb1 = __ldg(pb + 8);
    const float4 fc0 = __ldg(pc + 0), fc1 = __ldg(pc + 8);
    const float4 fd0 = __ldg(pd + 0), fd1 = __ldg(pd + 8);

    float4 r0, r1;
    r0.x = wam * fa0.x + wbm * fb0.x + wcm * fc0.x + wdm * fd0.x;
    r0.y = wam * fa0.y + wbm * fb0.y + wcm * fc0.y + wdm * fd0.y;
    r0.z = wam * fa0.z + wbm * fb0.z + wcm * fc0.z + wdm * fd0.z;
    r0.w = wam * fa0.w + wbm * fb0.w + wcm * fc0.w + wdm * fd0.w;

    r1.x = wam * fa1.x + wbm * fb1.x + wcm * fc1.x + wdm * fd1.x;
    r1.y = wam * fa1.y + wbm * fb1.y + wcm * fc1.y + wdm * fd1.y;
    r1.z = wam * fa1.z + wbm * fb1.z + wcm * fc1.z + wdm * fd1.z;
    r1.w = wam * fa1.w + wbm * fb1.w + wcm * fc1.w + wdm * fd1.w;

    // Write-through stores: bypass L2 for the output stream, keeping L2
    // capacity/bandwidth exclusively for the gather reuse.
    float4* po = out + pix * CH4 + lane;
    __stwt(po + 0, r0);
    __stwt(po + 8, r1);
}

extern "C" void kernel_launch(void* const* d_in, const int* in_sizes, int n_in,
                              void* d_out, int out_size)
{
    const float2* flow = (const float2*)d_in[0];   // w: [B,H,W,2]
    const float4* feat = (const float4*)d_in[1];   // feature: [B,H,W,C]
    const float*  mask = (const float*)d_in[2];    // mask: [H,W]
    float4* out = (float4*)d_out;

    dim3 grid(WW / PIXB, HH, BB);                  // (64, 384, 4)
    warp_bilinear_kernel<<<grid, THREADS>>>(flow, feat, mask, out);
}